// round 1
// baseline (speedup 1.0000x reference)
#include <cuda_runtime.h>

#define GDIM 7
#define GG 49           // G*G
#define NA 3            // anchors
#define NWARPS 8        // warps per block (one warp per sample)
#define MAXBLOCKS 8192  // 65536 / NWARPS

__device__ double g_partials[MAXBLOCKS];

__device__ __forceinline__ float bce_f(float p, float t) {
    // -(t*log(p) + (1-t)*log(1-p))
    return -(t * __logf(p) + (1.0f - t) * __logf(1.0f - p));
}

__global__ void __launch_bounds__(32 * NWARPS)
loss_main_kernel(const float* __restrict__ bboxp,   // (N,15,7,7)
                 const float* __restrict__ clsp,    // (N,2)
                 const float* __restrict__ bbox,    // (N,5,7,7)
                 const long long* __restrict__ cls, // (N,)
                 int N)
{
    const unsigned FULL = 0xffffffffu;
    const int warp = threadIdx.x >> 5;
    const int l    = threadIdx.x & 31;
    const int b    = blockIdx.x * NWARPS + warp;

    float tot = 0.0f;

    if (b < N) {
        const float* bb = bbox  + (size_t)b * (5 * GG);
        const float* bp = bboxp + (size_t)b * (15 * GG);

        // ---- Phase 1: argmax over probs = bbox[b,0,:,:] (first-occurrence ties) ----
        float p0 = (l      < GG) ? bb[l]      : -1e30f;
        float p1 = (l + 32 < GG) ? bb[l + 32] : -1e30f;
        float v  = p0;
        int   idx = l;
        if (p1 > v) { v = p1; idx = l + 32; }
        #pragma unroll
        for (int off = 16; off; off >>= 1) {
            float ov = __shfl_xor_sync(FULL, v, off);
            int   oi = __shfl_xor_sync(FULL, idx, off);
            if (ov > v || (ov == v && oi < idx)) { v = ov; idx = oi; }
        }
        const int m = idx;
        const int gi = m / GDIM, gj = m % GDIM;
        const float jf  = (float)gj;
        const float if_ = (float)gi;

        // ---- Phase 2: gather the 19 cell values (spread over lanes, broadcast) ----
        float g = 0.0f;
        if (l < 15)       g = bp[l * GG + m];          // cell_pr: 15 channels
        else if (l < 19)  g = bb[(l - 14) * GG + m];   // cell_gt channels 1..4
        float pr[15];
        #pragma unroll
        for (int c = 0; c < 15; c++) pr[c] = __shfl_sync(FULL, g, c);
        const float gt1 = __shfl_sync(FULL, g, 15);
        const float gt2 = __shfl_sync(FULL, g, 16);
        const float gt3 = __shfl_sync(FULL, g, 17);
        const float gt4 = __shfl_sync(FULL, g, 18);

        // ---- IoU best-anchor selection (computed redundantly on all lanes) ----
        const float tx  = (gt1 + jf)  / 7.0f;
        const float ty  = (gt2 + if_) / 7.0f;
        const float tx1 = tx - gt3 * 0.5f, tx2 = tx + gt3 * 0.5f;
        const float ty1 = ty - gt4 * 0.5f, ty2 = ty + gt4 * 0.5f;
        const float tarea = (tx2 - tx1) * (ty2 - ty1);

        float best_iou = -1e30f;
        int   best = 0;
        #pragma unroll
        for (int a = 0; a < NA; a++) {
            float ax  = (pr[5 * a + 1] + jf)  / 7.0f;
            float ay  = (pr[5 * a + 2] + if_) / 7.0f;
            float aw  = pr[5 * a + 3], ah = pr[5 * a + 4];
            float ax1 = ax - aw * 0.5f, ax2 = ax + aw * 0.5f;
            float ay1 = ay - ah * 0.5f, ay2 = ay + ah * 0.5f;
            float iw = fminf(ax2, tx2) - fmaxf(ax1, tx1); iw = fmaxf(iw, 0.0f);
            float ih = fminf(ay2, ty2) - fmaxf(ay1, ty1); ih = fmaxf(ih, 0.0f);
            float inter = iw * ih;
            float uni   = (ax2 - ax1) * (ay2 - ay1) + tarea - inter;
            float iou   = inter / (uni + 1e-9f);
            if (iou > best_iou) { best_iou = iou; best = a; }
        }

        // ---- coord + size losses (only lane 0 will contribute them) ----
        const float coord = bce_f(pr[5 * best + 1], gt1) + bce_f(pr[5 * best + 2], gt2);
        const float size_ = fabsf(__logf(pr[5 * best + 3]) - __logf(gt3))
                          + fabsf(__logf(pr[5 * best + 4]) - __logf(gt4));

        // ---- Phase 3: prob BCE over 3 anchor-prob channels x 49 cells ----
        float s = 0.0f;
        #pragma unroll
        for (int a = 0; a < NA; a++) {
            const float* pch = bp + a * (5 * GG);   // channels 0, 5, 10
            const bool isb = (a == best);
            if (l < GG) {
                float p = pch[l];
                float t = isb ? p0 : 0.0f;
                s += bce_f(p, t);
            }
            if (l + 32 < GG) {
                float p = pch[l + 32];
                float t = isb ? p1 : 0.0f;
                s += bce_f(p, t);
            }
        }

        // ---- CE (lane 0) ----
        float extra = 0.0f;
        if (l == 0) {
            float c0 = clsp[2 * (size_t)b];
            float c1 = clsp[2 * (size_t)b + 1];
            long long y = cls[b];           // 1 or 2
            float mx  = fmaxf(c0, c1);
            float lse = mx + __logf(__expf(c0 - mx) + __expf(c1 - mx));
            float sel = (y == 1) ? c0 : c1;
            float ce  = -(sel - lse);
            extra = coord + size_ + ce * (1.0f / (float)N);
        }

        tot = s * (1.0f / ((float)N * 49.0f)) + extra;
    }

    // ---- warp reduce ----
    #pragma unroll
    for (int off = 16; off; off >>= 1)
        tot += __shfl_xor_sync(FULL, tot, off);

    // ---- block reduce ----
    __shared__ float wsum[NWARPS];
    if (l == 0) wsum[warp] = tot;
    __syncthreads();
    if (warp == 0) {
        float x = (l < NWARPS) ? wsum[l] : 0.0f;
        #pragma unroll
        for (int off = NWARPS / 2; off; off >>= 1)
            x += __shfl_xor_sync(FULL, x, off);
        if (l == 0) g_partials[blockIdx.x] = (double)x;
    }
}

__global__ void __launch_bounds__(1024)
loss_reduce_kernel(float* __restrict__ out, int nparts)
{
    const unsigned FULL = 0xffffffffu;
    __shared__ double sh[32];
    double s = 0.0;
    for (int k = threadIdx.x; k < nparts; k += blockDim.x)
        s += g_partials[k];
    #pragma unroll
    for (int off = 16; off; off >>= 1)
        s += __shfl_xor_sync(FULL, s, off);
    int w = threadIdx.x >> 5, l = threadIdx.x & 31;
    if (l == 0) sh[w] = s;
    __syncthreads();
    if (w == 0) {
        double x = (l < 32) ? sh[l] : 0.0;
        #pragma unroll
        for (int off = 16; off; off >>= 1)
            x += __shfl_xor_sync(FULL, x, off);
        if (l == 0) out[0] = (float)x;
    }
}

extern "C" void kernel_launch(void* const* d_in, const int* in_sizes, int n_in,
                              void* d_out, int out_size)
{
    const float*     bboxp = (const float*)d_in[0];     // (N,15,7,7)
    const float*     clsp  = (const float*)d_in[1];     // (N,2)
    const float*     bbox  = (const float*)d_in[2];     // (N,5,7,7)
    const long long* cls   = (const long long*)d_in[3]; // (N,) int64

    const int N = in_sizes[3];
    int nblocks = (N + NWARPS - 1) / NWARPS;
    if (nblocks > MAXBLOCKS) nblocks = MAXBLOCKS;  // N is 65536 -> 8192 blocks

    loss_main_kernel<<<nblocks, 32 * NWARPS>>>(bboxp, clsp, bbox, cls, N);
    loss_reduce_kernel<<<1, 1024>>>((float*)d_out, nblocks);
}

// round 2
// speedup vs baseline: 1.0885x; 1.0885x over previous
#include <cuda_runtime.h>

#define GDIM 7
#define GG 49
#define NA 3
#define NWARPS 16            // warps (= samples) per block

__device__ double   g_acc   = 0.0;
__device__ unsigned g_count = 0u;

__global__ void __launch_bounds__(32 * NWARPS)
loss_fused_kernel(const float* __restrict__ bboxp,   // (N,15,7,7)
                  const float* __restrict__ clsp,    // (N,2)
                  const float* __restrict__ bbox,    // (N,5,7,7)
                  const long long* __restrict__ cls, // (N,)
                  float* __restrict__ out,
                  int N)
{
    const unsigned FULL = 0xffffffffu;
    const int warp = threadIdx.x >> 5;
    const int l    = threadIdx.x & 31;
    const int b    = blockIdx.x * NWARPS + warp;

    float tot = 0.0f;

    if (b < N) {
        const float* bb = bbox  + (size_t)b * (5 * GG);
        const float* bp = bboxp + (size_t)b * (15 * GG);

        // ---- issue ALL independent loads up front ----
        const bool hi = (l < GG - 32);                 // l < 17
        float p0 = bb[l];                              // probs cell l
        float p1 = hi ? bb[l + 32] : -1e30f;           // probs cell l+32

        float q0[NA], q1[NA];
        #pragma unroll
        for (int a = 0; a < NA; a++) {                 // channels 0,5,10 of bbox_
            const float* pch = bp + a * (5 * GG);
            q0[a] = pch[l];
            q1[a] = hi ? pch[l + 32] : 0.5f;
        }

        float c0 = 0.f, c1 = 0.f; long long y = 1;
        if (l == 0) {
            c0 = clsp[2 * (size_t)b];
            c1 = clsp[2 * (size_t)b + 1];
            y  = cls[b];
        }

        // ---- argmax over probs (first-occurrence tie-break) ----
        float v = p0; int idx = l;
        if (p1 > v) { v = p1; idx = l + 32; }
        #pragma unroll
        for (int off = 16; off; off >>= 1) {
            float ov = __shfl_xor_sync(FULL, v, off);
            int   oi = __shfl_xor_sync(FULL, idx, off);
            if (ov > v || (ov == v && oi < idx)) { v = ov; idx = oi; }
        }
        const int m = idx;
        const float jf  = (float)(m % GDIM);
        const float if_ = (float)(m / GDIM);

        // ---- gather 19 cell values at cell m, broadcast via shuffles ----
        float g = 0.0f;
        if (l < 15)      g = bp[l * GG + m];           // cell_pr channels 0..14
        else if (l < 19) g = bb[(l - 14) * GG + m];    // cell_gt channels 1..4
        float pr[15];
        #pragma unroll
        for (int c = 0; c < 15; c++) pr[c] = __shfl_sync(FULL, g, c);
        const float gt1 = __shfl_sync(FULL, g, 15);
        const float gt2 = __shfl_sync(FULL, g, 16);
        const float gt3 = __shfl_sync(FULL, g, 17);
        const float gt4 = __shfl_sync(FULL, g, 18);

        // ---- per-anchor BCE partials (independent of `best`) ----
        // S0[a] = sum -log(1-q);  S1[a] = sum bce(q, probs_cell)
        const float p0c = fmaxf(p0, 0.0f);             // real prob (p0 valid for all l<32)
        float S0[NA], S1[NA];
        #pragma unroll
        for (int a = 0; a < NA; a++) {
            float lq  = __logf(q0[a]);
            float l1q = __logf(1.0f - q0[a]);
            float s0 = -l1q;
            float s1 = -(p0c * lq + (1.0f - p0c) * l1q);
            if (hi) {
                float lqb  = __logf(q1[a]);
                float l1qb = __logf(1.0f - q1[a]);
                s0 += -l1qb;
                s1 += -(p1 * lqb + (1.0f - p1) * l1qb);
            }
            S0[a] = s0; S1[a] = s1;
        }

        // ---- IoU best-anchor selection (uniform across warp) ----
        const float inv7 = 1.0f / 7.0f;
        const float tx  = (gt1 + jf)  * inv7;
        const float ty  = (gt2 + if_) * inv7;
        const float tx1 = tx - gt3 * 0.5f, tx2 = tx + gt3 * 0.5f;
        const float ty1 = ty - gt4 * 0.5f, ty2 = ty + gt4 * 0.5f;
        const float tarea = (tx2 - tx1) * (ty2 - ty1);

        float best_iou = -1e30f; int best = 0;
        #pragma unroll
        for (int a = 0; a < NA; a++) {
            float ax  = (pr[5 * a + 1] + jf)  * inv7;
            float ay  = (pr[5 * a + 2] + if_) * inv7;
            float aw  = pr[5 * a + 3], ah = pr[5 * a + 4];
            float ax1 = ax - aw * 0.5f, ax2 = ax + aw * 0.5f;
            float ay1 = ay - ah * 0.5f, ay2 = ay + ah * 0.5f;
            float iw = fmaxf(fminf(ax2, tx2) - fmaxf(ax1, tx1), 0.0f);
            float ih = fmaxf(fminf(ay2, ty2) - fmaxf(ay1, ty1), 0.0f);
            float inter = iw * ih;
            float uni   = (ax2 - ax1) * (ay2 - ay1) + tarea - inter;
            float iou   = __fdividef(inter, uni + 1e-9f);
            if (iou > best_iou) { best_iou = iou; best = a; }
        }

        // combine BCE partials: all S0 plus correction for best anchor
        float s = S0[0] + S0[1] + S0[2];
        float corr = S1[0] - S0[0];
        if (best == 1) corr = S1[1] - S0[1];
        if (best == 2) corr = S1[2] - S0[2];
        s += corr;

        // ---- coord + size + CE on lane 0 ----
        float extra = 0.0f;
        if (l == 0) {
            float bx = pr[5 * best + 1], by = pr[5 * best + 2];
            float bw = pr[5 * best + 3], bh = pr[5 * best + 4];
            float coord = -(gt1 * __logf(bx) + (1.0f - gt1) * __logf(1.0f - bx))
                        + -(gt2 * __logf(by) + (1.0f - gt2) * __logf(1.0f - by));
            float size_ = fabsf(__logf(bw) - __logf(gt3))
                        + fabsf(__logf(bh) - __logf(gt4));
            float mx  = fmaxf(c0, c1);
            float lse = mx + __logf(__expf(c0 - mx) + __expf(c1 - mx));
            float sel = (y == 1) ? c0 : c1;
            float ce  = lse - sel;
            extra = coord + size_ + ce * (1.0f / (float)N);
        }

        tot = s * (1.0f / ((float)N * 49.0f)) + extra;
    }

    // ---- warp reduce ----
    #pragma unroll
    for (int off = 16; off; off >>= 1)
        tot += __shfl_xor_sync(FULL, tot, off);

    // ---- block reduce -> one double atomic per block ----
    __shared__ float wsum[NWARPS];
    if (l == 0) wsum[warp] = tot;
    __syncthreads();
    if (threadIdx.x == 0) {
        float x = 0.0f;
        #pragma unroll
        for (int w = 0; w < NWARPS; w++) x += wsum[w];
        atomicAdd(&g_acc, (double)x);
        __threadfence();
        unsigned old = atomicInc(&g_count, gridDim.x - 1);
        if (old == gridDim.x - 1) {
            // last block: read+reset accumulator atomically, emit result
            unsigned long long raw =
                atomicExch((unsigned long long*)&g_acc, 0ull);
            out[0] = (float)__longlong_as_double(raw);
        }
    }
}

extern "C" void kernel_launch(void* const* d_in, const int* in_sizes, int n_in,
                              void* d_out, int out_size)
{
    const float*     bboxp = (const float*)d_in[0];     // (N,15,7,7)
    const float*     clsp  = (const float*)d_in[1];     // (N,2)
    const float*     bbox  = (const float*)d_in[2];     // (N,5,7,7)
    const long long* cls   = (const long long*)d_in[3]; // (N,)

    const int N = in_sizes[3];
    const int nblocks = (N + NWARPS - 1) / NWARPS;

    loss_fused_kernel<<<nblocks, 32 * NWARPS>>>(bboxp, clsp, bbox, cls,
                                                (float*)d_out, N);
}

// round 3
// speedup vs baseline: 1.4340x; 1.3174x over previous
#include <cuda_runtime.h>

#define GDIM 7
#define GG 49
#define NWARPS 8             // warps (= samples) per block

__device__ double   g_acc   = 0.0;
__device__ unsigned g_count = 0u;

__global__ void __launch_bounds__(32 * NWARPS, 8)
loss_fused_kernel(const float* __restrict__ bboxp,   // (N,15,7,7)
                  const float* __restrict__ clsp,    // (N,2)
                  const float* __restrict__ bbox,    // (N,5,7,7)
                  const long long* __restrict__ cls, // (N,)
                  float* __restrict__ out,
                  int N)
{
    const unsigned FULL = 0xffffffffu;
    const int warp = threadIdx.x >> 5;
    const int l    = threadIdx.x & 31;
    const int b    = blockIdx.x * NWARPS + warp;

    float tot = 0.0f;

    if (b < N) {
        const float* bb = bbox  + (size_t)b * (5 * GG);
        const float* bp = bboxp + (size_t)b * (15 * GG);
        const bool hi = (l < GG - 32);                  // l < 17

        // ---- issue ALL independent loads up front (8 LDG, high MLP) ----
        float p0  = bb[l];
        float p1  = hi ? bb[l + 32] : -1e30f;
        float q0a = bp[l],            q1a = hi ? bp[l + 32]           : 0.5f;
        float q0b = bp[5*GG + l],     q1b = hi ? bp[5*GG + l + 32]    : 0.5f;
        float q0c = bp[10*GG + l],    q1c = hi ? bp[10*GG + l + 32]   : 0.5f;

        float c0 = 0.f, c1 = 0.f; long long y = 1;
        if (l == 0) {
            c0 = clsp[2 * (size_t)b];
            c1 = clsp[2 * (size_t)b + 1];
            y  = cls[b];
        }

        // ---- argmax over probs (first-occurrence ties) ----
        float v = p0; int idx = l;
        if (p1 > v) { v = p1; idx = l + 32; }
        #pragma unroll
        for (int off = 16; off; off >>= 1) {
            float ov = __shfl_xor_sync(FULL, v, off);
            int   oi = __shfl_xor_sync(FULL, idx, off);
            if (ov > v || (ov == v && oi < idx)) { v = ov; idx = oi; }
        }
        const int m = idx;
        const float jf  = (float)(m % GDIM);
        const float if_ = (float)(m / GDIM);

        // ---- dependent gather: 19 cell-m values, one per lane ----
        float g = 0.0f;
        if (l < 15)      g = bp[l * GG + m];            // cell_pr channels 0..14
        else if (l < 19) g = bb[(l - 14) * GG + m];     // cell_gt channels 1..4

        // ---- independent log(1-q) work overlaps the gather latency ----
        float l1a = __logf(1.0f - q0a);
        float l1b = __logf(1.0f - q0b);
        float l1c = __logf(1.0f - q0c);
        float s = -(l1a + l1b + l1c);
        float m1a = 0.f, m1b = 0.f, m1c = 0.f;
        if (hi) {
            m1a = __logf(1.0f - q1a);
            m1b = __logf(1.0f - q1b);
            m1c = __logf(1.0f - q1c);
            s -= (m1a + m1b + m1c);
        }

        // ---- broadcast gt, distribute anchors to lanes 0..2 ----
        const float gt1 = __shfl_sync(FULL, g, 15);
        const float gt2 = __shfl_sync(FULL, g, 16);
        const float gt3 = __shfl_sync(FULL, g, 17);
        const float gt4 = __shfl_sync(FULL, g, 18);

        const int al = 5 * min(l, 2);                   // lane a<3 owns anchor a
        const float a1 = __shfl_sync(FULL, g, al + 1);
        const float a2 = __shfl_sync(FULL, g, al + 2);
        const float a3 = __shfl_sync(FULL, g, al + 3);
        const float a4 = __shfl_sync(FULL, g, al + 4);

        // ---- IoU (each of lanes 0..2 computes one anchor) ----
        const float inv7 = 1.0f / 7.0f;
        const float tx  = (gt1 + jf)  * inv7;
        const float ty  = (gt2 + if_) * inv7;
        const float tx1 = tx - gt3 * 0.5f, tx2 = tx + gt3 * 0.5f;
        const float ty1 = ty - gt4 * 0.5f, ty2 = ty + gt4 * 0.5f;
        const float tarea = (tx2 - tx1) * (ty2 - ty1);

        const float ax  = (a1 + jf)  * inv7;
        const float ay  = (a2 + if_) * inv7;
        const float ax1 = ax - a3 * 0.5f, ax2 = ax + a3 * 0.5f;
        const float ay1 = ay - a4 * 0.5f, ay2 = ay + a4 * 0.5f;
        float iw = fmaxf(fminf(ax2, tx2) - fmaxf(ax1, tx1), 0.0f);
        float ih = fmaxf(fminf(ay2, ty2) - fmaxf(ay1, ty1), 0.0f);
        float inter = iw * ih;
        float uni   = (ax2 - ax1) * (ay2 - ay1) + tarea - inter;
        float iou   = __fdividef(inter, uni + 1e-9f);

        const float i0 = __shfl_sync(FULL, iou, 0);
        const float i1 = __shfl_sync(FULL, iou, 1);
        const float i2 = __shfl_sync(FULL, iou, 2);
        int best = 0; float bi = i0;
        if (i1 > bi) { best = 1; bi = i1; }
        if (i2 > bi) { best = 2; }

        // ---- BCE correction for best anchor: -p * logit(q_best) ----
        float qb0 = (best == 0) ? q0a : (best == 1) ? q0b : q0c;
        float lb0 = (best == 0) ? l1a : (best == 1) ? l1b : l1c;
        s -= p0 * (__logf(qb0) - lb0);
        if (hi) {
            float qb1 = (best == 0) ? q1a : (best == 1) ? q1b : q1c;
            float lb1 = (best == 0) ? m1a : (best == 1) ? m1b : m1c;
            s -= p1 * (__logf(qb1) - lb1);
        }

        // ---- best box values to lane 0 ----
        const int bo = 5 * best;
        const float bx = __shfl_sync(FULL, g, bo + 1);
        const float by = __shfl_sync(FULL, g, bo + 2);
        const float bw = __shfl_sync(FULL, g, bo + 3);
        const float bh = __shfl_sync(FULL, g, bo + 4);

        float extra = 0.0f;
        if (l == 0) {
            float coord = -(gt1 * __logf(bx) + (1.0f - gt1) * __logf(1.0f - bx))
                        + -(gt2 * __logf(by) + (1.0f - gt2) * __logf(1.0f - by));
            float size_ = fabsf(__logf(bw) - __logf(gt3))
                        + fabsf(__logf(bh) - __logf(gt4));
            float mx  = fmaxf(c0, c1);
            float lse = mx + __logf(__expf(c0 - mx) + __expf(c1 - mx));
            float sel = (y == 1) ? c0 : c1;
            float ce  = lse - sel;
            extra = coord + size_ + ce * (1.0f / (float)N);
        }

        tot = s * (1.0f / ((float)N * 49.0f)) + extra;
    }

    // ---- warp reduce ----
    #pragma unroll
    for (int off = 16; off; off >>= 1)
        tot += __shfl_xor_sync(FULL, tot, off);

    // ---- block reduce -> one double atomic per block ----
    __shared__ float wsum[NWARPS];
    if (l == 0) wsum[warp] = tot;
    __syncthreads();
    if (threadIdx.x == 0) {
        float x = 0.0f;
        #pragma unroll
        for (int w = 0; w < NWARPS; w++) x += wsum[w];
        atomicAdd(&g_acc, (double)x);
        __threadfence();
        unsigned old = atomicInc(&g_count, gridDim.x - 1);
        if (old == gridDim.x - 1) {
            unsigned long long raw =
                atomicExch((unsigned long long*)&g_acc, 0ull);
            out[0] = (float)__longlong_as_double(raw);
        }
    }
}

extern "C" void kernel_launch(void* const* d_in, const int* in_sizes, int n_in,
                              void* d_out, int out_size)
{
    const float*     bboxp = (const float*)d_in[0];     // (N,15,7,7)
    const float*     clsp  = (const float*)d_in[1];     // (N,2)
    const float*     bbox  = (const float*)d_in[2];     // (N,5,7,7)
    const long long* cls   = (const long long*)d_in[3]; // (N,)

    const int N = in_sizes[3];
    const int nblocks = (N + NWARPS - 1) / NWARPS;

    loss_fused_kernel<<<nblocks, 32 * NWARPS>>>(bboxp, clsp, bbox, cls,
                                                (float*)d_out, N);
}

// round 4
// speedup vs baseline: 1.4451x; 1.0078x over previous
#include <cuda_runtime.h>

#define GDIM 7
#define GG 49
#define NWARPS 8             // warps (= samples) per block

__device__ double   g_acc   = 0.0;
__device__ unsigned g_count = 0u;

__global__ void __launch_bounds__(32 * NWARPS, 8)
loss_fused_kernel(const float* __restrict__ bboxp,   // (N,15,7,7)
                  const float* __restrict__ clsp,    // (N,2)
                  const float* __restrict__ bbox,    // (N,5,7,7)
                  const long long* __restrict__ cls, // (N,)
                  float* __restrict__ out,
                  int N)
{
    const unsigned FULL = 0xffffffffu;
    const int warp = threadIdx.x >> 5;
    const int l    = threadIdx.x & 31;
    const int b    = blockIdx.x * NWARPS + warp;

    float tot = 0.0f;

    if (b < N) {
        const float* bb = bbox  + (size_t)b * (5 * GG);
        const float* bp = bboxp + (size_t)b * (15 * GG);
        const bool hi = (l < GG - 32);                  // l < 17

        // ---- all independent loads up front ----
        float p0  = bb[l];
        float p1  = hi ? bb[l + 32] : 0.0f;
        float q0a = bp[l],          q1a = hi ? bp[l + 32]         : 0.5f;
        float q0b = bp[5*GG + l],   q1b = hi ? bp[5*GG + l + 32]  : 0.5f;
        float q0c = bp[10*GG + l],  q1c = hi ? bp[10*GG + l + 32] : 0.5f;

        float c0 = 0.f, c1 = 0.f; long long y = 1;
        if (l == 0) {
            c0 = clsp[2 * (size_t)b];
            c1 = clsp[2 * (size_t)b + 1];
            y  = cls[b];
        }

        // ---- exact argmax: REDUX on positive-float bits + ballots ----
        const unsigned b0 = __float_as_uint(p0);              // probs > 0
        const unsigned b1 = hi ? __float_as_uint(p1) : 0u;
        const unsigned vmax = __reduce_max_sync(FULL, b0 > b1 ? b0 : b1);
        const unsigned bal0 = __ballot_sync(FULL, b0 == vmax);
        const unsigned bal1 = __ballot_sync(FULL, b1 == vmax);
        const int m = bal0 ? (__ffs(bal0) - 1) : (32 + __ffs(bal1) - 1);
        const float jf  = (float)(m % GDIM);
        const float if_ = (float)(m / GDIM);

        // ---- dependent gather: 19 cell-m values, one per lane ----
        float g = 0.0f;
        if (l < 15)      g = bp[l * GG + m];            // cell_pr channels 0..14
        else if (l < 19) g = bb[(l - 14) * GG + m];     // cell_gt channels 1..4

        // ---- independent log(1-q) work overlaps the gather latency ----
        float l1a = __logf(1.0f - q0a);
        float l1b = __logf(1.0f - q0b);
        float l1c = __logf(1.0f - q0c);
        float s = -(l1a + l1b + l1c);
        float m1a = 0.f, m1b = 0.f, m1c = 0.f;
        if (hi) {
            m1a = __logf(1.0f - q1a);
            m1b = __logf(1.0f - q1b);
            m1c = __logf(1.0f - q1c);
            s -= (m1a + m1b + m1c);
        }

        // ---- broadcast gt; lanes 0..2 own one anchor each ----
        const float gt1 = __shfl_sync(FULL, g, 15);
        const float gt2 = __shfl_sync(FULL, g, 16);
        const float gt3 = __shfl_sync(FULL, g, 17);
        const float gt4 = __shfl_sync(FULL, g, 18);

        const int al = 5 * min(l, 2);
        const float a1 = __shfl_sync(FULL, g, al + 1);
        const float a2 = __shfl_sync(FULL, g, al + 2);
        const float a3 = __shfl_sync(FULL, g, al + 3);
        const float a4 = __shfl_sync(FULL, g, al + 4);

        // ---- IoU on lanes 0..2; winner via one packed REDUX ----
        const float inv7 = 1.0f / 7.0f;
        const float tx  = (gt1 + jf)  * inv7;
        const float ty  = (gt2 + if_) * inv7;
        const float tx1 = tx - gt3 * 0.5f, tx2 = tx + gt3 * 0.5f;
        const float ty1 = ty - gt4 * 0.5f, ty2 = ty + gt4 * 0.5f;
        const float tarea = (tx2 - tx1) * (ty2 - ty1);

        const float ax  = (a1 + jf)  * inv7;
        const float ay  = (a2 + if_) * inv7;
        const float ax1 = ax - a3 * 0.5f, ax2 = ax + a3 * 0.5f;
        const float ay1 = ay - a4 * 0.5f, ay2 = ay + a4 * 0.5f;
        float iw = fmaxf(fminf(ax2, tx2) - fmaxf(ax1, tx1), 0.0f);
        float ih = fmaxf(fminf(ay2, ty2) - fmaxf(ay1, ty1), 0.0f);
        float inter = iw * ih;
        float uni   = (ax2 - ax1) * (ay2 - ay1) + tarea - inter;
        float iou   = __fdividef(inter, uni + 1e-9f);

        // key: high 30 bits of (non-negative) iou | (3 - anchor); max -> best iou,
        // smallest anchor index on ties (matches jnp.argmax first-occurrence)
        unsigned key = (l < 3) ? ((__float_as_uint(iou) & ~3u) | (3u - l)) : 0u;
        key = __reduce_max_sync(FULL, key);
        const int best = 3 - (int)(key & 3u);

        // ---- BCE correction for best anchor: -p * (log q - log(1-q)) ----
        float qb0 = (best == 0) ? q0a : (best == 1) ? q0b : q0c;
        float lb0 = (best == 0) ? l1a : (best == 1) ? l1b : l1c;
        s -= p0 * (__logf(qb0) - lb0);
        if (hi) {
            float qb1 = (best == 0) ? q1a : (best == 1) ? q1b : q1c;
            float lb1 = (best == 0) ? m1a : (best == 1) ? m1b : m1c;
            s -= p1 * (__logf(qb1) - lb1);
        }

        tot = s * (1.0f / ((float)N * 49.0f));

        // ---- coord + size computed on the winning anchor's lane ----
        if (l == best) {
            float coord = -(gt1 * __logf(a1) + (1.0f - gt1) * __logf(1.0f - a1))
                        + -(gt2 * __logf(a2) + (1.0f - gt2) * __logf(1.0f - a2));
            float size_ = fabsf(__logf(a3) - __logf(gt3))
                        + fabsf(__logf(a4) - __logf(gt4));
            tot += coord + size_;
        }

        // ---- CE on lane 0 ----
        if (l == 0) {
            float mx  = fmaxf(c0, c1);
            float lse = mx + __logf(__expf(c0 - mx) + __expf(c1 - mx));
            float sel = (y == 1) ? c0 : c1;
            tot += (lse - sel) * (1.0f / (float)N);
        }
    }

    // ---- warp reduce ----
    #pragma unroll
    for (int off = 16; off; off >>= 1)
        tot += __shfl_xor_sync(FULL, tot, off);

    // ---- block reduce -> one double atomic per block ----
    __shared__ float wsum[NWARPS];
    if (l == 0) wsum[warp] = tot;
    __syncthreads();
    if (threadIdx.x == 0) {
        float x = 0.0f;
        #pragma unroll
        for (int w = 0; w < NWARPS; w++) x += wsum[w];
        atomicAdd(&g_acc, (double)x);
        __threadfence();
        unsigned old = atomicInc(&g_count, gridDim.x - 1);
        if (old == gridDim.x - 1) {
            unsigned long long raw =
                atomicExch((unsigned long long*)&g_acc, 0ull);
            out[0] = (float)__longlong_as_double(raw);
        }
    }
}

extern "C" void kernel_launch(void* const* d_in, const int* in_sizes, int n_in,
                              void* d_out, int out_size)
{
    const float*     bboxp = (const float*)d_in[0];     // (N,15,7,7)
    const float*     clsp  = (const float*)d_in[1];     // (N,2)
    const float*     bbox  = (const float*)d_in[2];     // (N,5,7,7)
    const long long* cls   = (const long long*)d_in[3]; // (N,)

    const int N = in_sizes[3];
    const int nblocks = (N + NWARPS - 1) / NWARPS;

    loss_fused_kernel<<<nblocks, 32 * NWARPS>>>(bboxp, clsp, bbox, cls,
                                                (float*)d_out, N);
}